// round 10
// baseline (speedup 1.0000x reference)
#include <cuda_runtime.h>
#include <cuda_bf16.h>

// Contrastive loss v7 = v3 structure (best, 16.4us) + 256-bit row loads.
//   per pair p: sq = ||emb[a]-emb[b]||^2 ; d = sqrt(max(sq,1e-12))
//   loss_p = (1-i)*max(0,1-d)^2 + i*d^2 ; out = sum / (P+1e-10)
//
// v7 vs v3: rows loaded as 4 x LDG.256 (v8.b32, 32B/lane) instead of
// 8 x LDG.128 -> halves LDG instruction count & LSU dispatch-queue slots at
// IDENTICAL data-register cost (32 regs). evict_last immediate modifier is
// legal on v8.b32 (the exact form ptxas demanded in R8), kept since free.

#define D_DIM 512
#define WARPS_PER_BLOCK 8
#define THREADS_PER_BLOCK (WARPS_PER_BLOCK * 32)
#define BLOCKS_TARGET 1024           // 8192 warps -> 4 pairs/warp at P=32768
#define MAX_BLOCKS 16384

__device__ float        g_partials[MAX_BLOCKS];
__device__ unsigned int g_counter = 0;

__device__ __forceinline__ unsigned int atom_add_acqrel(unsigned int* p,
                                                        unsigned int v) {
    unsigned int old;
    asm volatile("atom.acq_rel.gpu.global.add.u32 %0, [%1], %2;"
                 : "=r"(old) : "l"(p), "r"(v) : "memory");
    return old;
}

// 32B read-only load (LDG.256) with L2 evict_last. 8 floats -> v[0..7].
__device__ __forceinline__ void ldg256(const float* __restrict__ p, float* v)
{
    unsigned r0, r1, r2, r3, r4, r5, r6, r7;
    asm("ld.global.nc.L2::evict_last.v8.b32 {%0,%1,%2,%3,%4,%5,%6,%7}, [%8];"
        : "=r"(r0), "=r"(r1), "=r"(r2), "=r"(r3),
          "=r"(r4), "=r"(r5), "=r"(r6), "=r"(r7)
        : "l"(p));
    v[0] = __uint_as_float(r0); v[1] = __uint_as_float(r1);
    v[2] = __uint_as_float(r2); v[3] = __uint_as_float(r3);
    v[4] = __uint_as_float(r4); v[5] = __uint_as_float(r5);
    v[6] = __uint_as_float(r6); v[7] = __uint_as_float(r7);
}

__global__ __launch_bounds__(THREADS_PER_BLOCK)
void contrastive_fused_kernel(const float* __restrict__ emb,
                              const int* __restrict__ pair_a,
                              const int* __restrict__ pair_b,
                              const int* __restrict__ pair_same,
                              float* __restrict__ out,
                              int P)
{
    const int warp_id     = threadIdx.x >> 5;
    const int lane        = threadIdx.x & 31;
    const int warp_global = blockIdx.x * WARPS_PER_BLOCK + warp_id;
    const int warp_stride = gridDim.x * WARPS_PER_BLOCK;

    float warp_loss = 0.0f;   // meaningful on lane 0 only

    int p  = warp_global;
    int ia = 0, ib = 0;
    if (p < P) { ia = __ldg(pair_a + p); ib = __ldg(pair_b + p); }

    while (p < P) {
        // Prefetch next pair's indices (hides idx->row dependent chain).
        const int p_next = p + warp_stride;
        int ia_next = 0, ib_next = 0;
        if (p_next < P) {
            ia_next = __ldg(pair_a + p_next);
            ib_next = __ldg(pair_b + p_next);
        }

        // Row base + per-lane 32B slice: row = 2048B; each warp-instruction
        // covers 1KB contiguous (32 lanes x 32B). 2 loads per row.
        const float* __restrict__ ra = emb + (size_t)ia * D_DIM + lane * 8;
        const float* __restrict__ rb = emb + (size_t)ib * D_DIM + lane * 8;

        float a0[8], a1[8], b0[8], b1[8];
        ldg256(ra,       a0);
        ldg256(ra + 256, a1);   // +1024B
        ldg256(rb,       b0);
        ldg256(rb + 256, b1);

        // ||a-b||^2 per lane.
        float s = 0.0f;
        #pragma unroll
        for (int k = 0; k < 8; ++k) {
            float d0 = a0[k] - b0[k];
            float d1 = a1[k] - b1[k];
            s += d0 * d0 + d1 * d1;
        }

        // Warp tree reduction (5 shfl).
        #pragma unroll
        for (int off = 16; off > 0; off >>= 1)
            s += __shfl_xor_sync(0xFFFFFFFFu, s, off);

        if (lane == 0) {
            float sq = fmaxf(s, 1e-12f);
            float d = sqrtf(sq);
            float i = (float)__ldg(pair_same + p);
            float h = fmaxf(0.0f, 1.0f - d);
            warp_loss += (1.0f - i) * h * h + i * d * d;
        }

        p  = p_next;
        ia = ia_next;
        ib = ib_next;
    }

    // Block reduction of per-warp losses.
    __shared__ float s_loss[WARPS_PER_BLOCK];
    __shared__ bool  s_is_last;
    if (lane == 0) s_loss[warp_id] = warp_loss;
    __syncthreads();

    if (threadIdx.x == 0) {
        float acc = 0.0f;
        #pragma unroll
        for (int w = 0; w < WARPS_PER_BLOCK; ++w) acc += s_loss[w];
        g_partials[blockIdx.x] = acc;
        unsigned int prev = atom_add_acqrel(&g_counter, 1u);  // release-orders store
        s_is_last = (prev == gridDim.x - 1);
        if (s_is_last) atomicExch(&g_counter, 0u);  // replay-safe self-reset
    }
    __syncthreads();

    // Last block: deterministic final reduction in fixed index order.
    if (s_is_last) {
        __shared__ float s_fin[THREADS_PER_BLOCK];
        float acc = 0.0f;
        for (int i = threadIdx.x; i < (int)gridDim.x; i += THREADS_PER_BLOCK)
            acc += g_partials[i];
        s_fin[threadIdx.x] = acc;
        __syncthreads();
        #pragma unroll
        for (int off = THREADS_PER_BLOCK / 2; off > 0; off >>= 1) {
            if (threadIdx.x < off) s_fin[threadIdx.x] += s_fin[threadIdx.x + off];
            __syncthreads();
        }
        if (threadIdx.x == 0)
            out[0] = s_fin[0] / ((float)P + 1e-10f);
    }
}

extern "C" void kernel_launch(void* const* d_in, const int* in_sizes, int n_in,
                              void* d_out, int out_size)
{
    const float* emb       = (const float*)d_in[0];
    const int*   pair_a    = (const int*)d_in[1];
    const int*   pair_b    = (const int*)d_in[2];
    const int*   pair_same = (const int*)d_in[3];
    float*       out       = (float*)d_out;

    const int P = in_sizes[1];  // element count of pair_a

    // Single balanced wave: at P=32768 -> 1024 blocks, exactly 4 pairs/warp.
    int warps_needed = (P + 3) / 4;  // target ~4 pairs per warp
    int num_blocks = (warps_needed + WARPS_PER_BLOCK - 1) / WARPS_PER_BLOCK;
    if (num_blocks > BLOCKS_TARGET) num_blocks = BLOCKS_TARGET;
    if (num_blocks < 1) num_blocks = 1;

    contrastive_fused_kernel<<<num_blocks, THREADS_PER_BLOCK>>>(
        emb, pair_a, pair_b, pair_same, out, P);
}